// round 2
// baseline (speedup 1.0000x reference)
#include <cuda_runtime.h>

#define Bb 2
#define Ls 2048
#define Dm 1024
#define Hh 16
#define Dk 64

// Scratch (allocation-free): Q,K,V,Z each B*H*L*Dk floats = 16 MB
__device__ float g_Q[Bb*Hh*Ls*Dk];
__device__ float g_K[Bb*Hh*Ls*Dk];
__device__ float g_V[Bb*Hh*Ls*Dk];
__device__ float g_Z[Bb*Hh*Ls*Dk];

// ---------------------------------------------------------------------------
// Projection: out[b,h,l,k] = sum_d X[b,l,d] * W[h,d,k] + bias[h,k]
// grid (L/64, B, H), 256 threads, 64x64 tile, BK=16, 4x4 micro-tile
// ---------------------------------------------------------------------------
__global__ void proj_kernel(const float* __restrict__ X,
                            const float* __restrict__ W,
                            const float* __restrict__ bias,
                            float* __restrict__ out)
{
    __shared__ float As[16][68];   // As[d][l]
    __shared__ float Bs[16][68];   // Bs[d][k]
    const int ltile = blockIdx.x, b = blockIdx.y, h = blockIdx.z;
    const int t = threadIdx.x, tx = t & 15, ty = t >> 4;
    const float* Xp = X + ((size_t)b*Ls + (size_t)ltile*64) * Dm;
    const float* Wp = W + (size_t)h*Dm*Dk;
    float acc[4][4] = {};
    for (int d0 = 0; d0 < Dm; d0 += 16) {
        {   // A tile 64(l) x 16(d), one float4/thread, store transposed
            int row = t >> 2, q = t & 3;
            float4 v = *(const float4*)(Xp + (size_t)row*Dm + d0 + q*4);
            As[q*4+0][row]=v.x; As[q*4+1][row]=v.y;
            As[q*4+2][row]=v.z; As[q*4+3][row]=v.w;
        }
        {   // B tile 16(d) x 64(k), natural layout
            int row = t >> 4, q = t & 15;
            float4 v = *(const float4*)(Wp + (size_t)(d0+row)*Dk + q*4);
            *(float4*)&Bs[row][q*4] = v;
        }
        __syncthreads();
#pragma unroll
        for (int d = 0; d < 16; d++) {
            float4 a  = *(const float4*)&As[d][ty*4];
            float4 b4 = *(const float4*)&Bs[d][tx*4];
            float av[4]={a.x,a.y,a.z,a.w}, bv[4]={b4.x,b4.y,b4.z,b4.w};
#pragma unroll
            for (int i=0;i<4;i++)
#pragma unroll
                for (int j=0;j<4;j++) acc[i][j] = fmaf(av[i], bv[j], acc[i][j]);
        }
        __syncthreads();
    }
    float* op = out + (((size_t)b*Hh + h)*Ls + (size_t)ltile*64)*Dk;
    const float* bp = bias + h*Dk;
#pragma unroll
    for (int j=0;j<4;j++) {
        float bj = bp[tx*4+j];
#pragma unroll
        for (int i=0;i<4;i++)
            op[(size_t)(ty*4+i)*Dk + tx*4+j] = acc[i][j] + bj;
    }
}

// ---------------------------------------------------------------------------
// Flash attention: per (b*h, 64-row Q tile). Online softmax, stream K/V.
// grid (L/64, B*H), 256 threads. Dynamic smem: 4 arrays of [64][68] floats.
// ---------------------------------------------------------------------------
__global__ void attn_kernel()
{
    extern __shared__ float smx[];
    float* QsT = smx;               // [64][68]  QsT[d][i]
    float* KsT = smx + 64*68;       // [64][68]  KsT[d][j]
    float* Vs  = smx + 2*64*68;     // [64][68]  Vs[j][v]
    float* Ps  = smx + 3*64*68;     // [64][68]  Ps[j][i]
    const int bh = blockIdx.y;
    const int i0 = blockIdx.x * 64;
    const float* Qp = g_Q + ((size_t)bh*Ls + i0)*Dk;
    const float* Kp = g_K + (size_t)bh*Ls*Dk;
    const float* Vp = g_V + (size_t)bh*Ls*Dk;
    const int t = threadIdx.x, tx = t & 15, ty = t >> 4;

    {   // load Q tile transposed
        int row = t >> 2, qd = t & 3;
#pragma unroll
        for (int k = 0; k < 4; k++) {
            int q = qd + k*4;
            float4 v = *(const float4*)(Qp + (size_t)row*Dk + q*4);
            QsT[(q*4+0)*68+row]=v.x; QsT[(q*4+1)*68+row]=v.y;
            QsT[(q*4+2)*68+row]=v.z; QsT[(q*4+3)*68+row]=v.w;
        }
    }
    float m[4], l[4], o[4][4];
#pragma unroll
    for (int r=0;r<4;r++){ m[r]=-1e30f; l[r]=0.f;
#pragma unroll
        for (int c=0;c<4;c++) o[r][c]=0.f; }

    for (int j0 = 0; j0 < Ls; j0 += 64) {
        __syncthreads();   // previous iter consumers of KsT/Vs/Ps done
        {   // load K (transposed) + V (natural)
            int row = t >> 2, qd = t & 3;
#pragma unroll
            for (int k = 0; k < 4; k++) {
                int q = qd + k*4;
                float4 kv = *(const float4*)(Kp + (size_t)(j0+row)*Dk + q*4);
                KsT[(q*4+0)*68+row]=kv.x; KsT[(q*4+1)*68+row]=kv.y;
                KsT[(q*4+2)*68+row]=kv.z; KsT[(q*4+3)*68+row]=kv.w;
                float4 vv = *(const float4*)(Vp + (size_t)(j0+row)*Dk + q*4);
                *(float4*)&Vs[row*68 + q*4] = vv;
            }
        }
        __syncthreads();
        // S = Q K^T  (4x4 per thread)
        float s[4][4] = {};
#pragma unroll 16
        for (int d = 0; d < 64; d++) {
            float4 a  = *(const float4*)&QsT[d*68 + ty*4];
            float4 b4 = *(const float4*)&KsT[d*68 + tx*4];
            float av[4]={a.x,a.y,a.z,a.w}, bv[4]={b4.x,b4.y,b4.z,b4.w};
#pragma unroll
            for (int i=0;i<4;i++)
#pragma unroll
                for (int j=0;j<4;j++) s[i][j] = fmaf(av[i], bv[j], s[i][j]);
        }
        // online softmax; row stats reduced over tx (lanes xor 1,2,4,8 stay in tx group)
#pragma unroll
        for (int r=0;r<4;r++) {
            float mx = -1e30f;
#pragma unroll
            for (int c=0;c<4;c++) { s[r][c] *= 0.125f; mx = fmaxf(mx, s[r][c]); }
#pragma unroll
            for (int off=8; off>=1; off>>=1)
                mx = fmaxf(mx, __shfl_xor_sync(0xffffffffu, mx, off));
            float mnew = fmaxf(m[r], mx);
            float corr = __expf(m[r] - mnew);
            float rs = 0.f;
#pragma unroll
            for (int c=0;c<4;c++) { s[r][c] = __expf(s[r][c] - mnew); rs += s[r][c]; }
#pragma unroll
            for (int off=8; off>=1; off>>=1)
                rs += __shfl_xor_sync(0xffffffffu, rs, off);
            l[r] = l[r]*corr + rs;
            m[r] = mnew;
#pragma unroll
            for (int c=0;c<4;c++) {
                o[r][c] *= corr;
                Ps[(tx*4+c)*68 + ty*4 + r] = s[r][c];   // store P transposed
            }
        }
        __syncthreads();
        // O += P V
#pragma unroll 16
        for (int j = 0; j < 64; j++) {
            float4 p4 = *(const float4*)&Ps[j*68 + ty*4];
            float4 v4 = *(const float4*)&Vs[j*68 + tx*4];
            float pv[4]={p4.x,p4.y,p4.z,p4.w}, vv[4]={v4.x,v4.y,v4.z,v4.w};
#pragma unroll
            for (int i=0;i<4;i++)
#pragma unroll
                for (int c=0;c<4;c++) o[i][c] = fmaf(pv[i], vv[c], o[i][c]);
        }
    }
    float* zp = g_Z + ((size_t)bh*Ls + i0)*Dk;
#pragma unroll
    for (int r=0;r<4;r++) {
        float inv = 1.f / l[r];
#pragma unroll
        for (int c=0;c<4;c++)
            zp[(size_t)(ty*4+r)*Dk + tx*4+c] = o[r][c]*inv;
    }
}

// ---------------------------------------------------------------------------
// Output projection: out[row, d] = sum_e Z[row, e] * Wo[d, e] + bo[d]
// Z[row=b*L+l][e=h*64+v] gathered from g_Z[b,h,l,v]. grid (64, 16).
// ---------------------------------------------------------------------------
__global__ void outproj_kernel(const float* __restrict__ Wo,
                               const float* __restrict__ bo,
                               float* __restrict__ out)
{
    __shared__ float As[16][68];   // As[e][row]
    __shared__ float Bs[16][68];   // Bs[e][d]
    const int rt = blockIdx.x, dt = blockIdx.y;
    const int t = threadIdx.x, tx = t & 15, ty = t >> 4;
    const int row0 = rt*64;
    const int b = row0 / Ls;        // 64 | 2048 so whole tile in one batch
    const int l0 = row0 % Ls;
    float acc[4][4] = {};
    for (int e0 = 0; e0 < Dm; e0 += 16) {
        const int h = e0 >> 6, v0 = e0 & 63;
        {   // A tile: Z rows, 16 e-cols (within one head)
            int r = t >> 2, q = t & 3;
            float4 v = *(const float4*)(g_Z + (((size_t)b*Hh + h)*Ls + l0 + r)*Dk + v0 + q*4);
            As[q*4+0][r]=v.x; As[q*4+1][r]=v.y; As[q*4+2][r]=v.z; As[q*4+3][r]=v.w;
        }
        {   // B tile: Wo[d][e], transposed to Bs[e][d]
            int d = t >> 2, q = t & 3;
            float4 v = *(const float4*)(Wo + (size_t)(dt*64+d)*Dm + e0 + q*4);
            Bs[q*4+0][d]=v.x; Bs[q*4+1][d]=v.y; Bs[q*4+2][d]=v.z; Bs[q*4+3][d]=v.w;
        }
        __syncthreads();
#pragma unroll
        for (int e = 0; e < 16; e++) {
            float4 a  = *(const float4*)&As[e][ty*4];
            float4 b4 = *(const float4*)&Bs[e][tx*4];
            float av[4]={a.x,a.y,a.z,a.w}, bv[4]={b4.x,b4.y,b4.z,b4.w};
#pragma unroll
            for (int i=0;i<4;i++)
#pragma unroll
                for (int j=0;j<4;j++) acc[i][j] = fmaf(av[i], bv[j], acc[i][j]);
        }
        __syncthreads();
    }
    float* op = out + (size_t)row0*Dm + dt*64;
#pragma unroll
    for (int j=0;j<4;j++) {
        float bj = bo[dt*64 + tx*4 + j];
#pragma unroll
        for (int i=0;i<4;i++)
            op[(size_t)(ty*4+i)*Dm + tx*4+j] = acc[i][j] + bj;
    }
}

// ---------------------------------------------------------------------------

extern "C" void kernel_launch(void* const* d_in, const int* in_sizes, int n_in,
                              void* d_out, int out_size)
{
    const float* X  = (const float*)d_in[0];
    const float* Wq = (const float*)d_in[1];
    const float* bq = (const float*)d_in[2];
    const float* Wk = (const float*)d_in[3];
    const float* bk = (const float*)d_in[4];
    const float* Wv = (const float*)d_in[5];
    const float* bv = (const float*)d_in[6];
    const float* Wo = (const float*)d_in[7];
    const float* bo = (const float*)d_in[8];
    float* out = (float*)d_out;

    float *gQ, *gK, *gV;
    cudaGetSymbolAddress((void**)&gQ, g_Q);
    cudaGetSymbolAddress((void**)&gK, g_K);
    cudaGetSymbolAddress((void**)&gV, g_V);

    const int attn_smem = 4*64*68*4;  // 69632 B > 48K -> needs attribute
    cudaFuncSetAttribute(attn_kernel, cudaFuncAttributeMaxDynamicSharedMemorySize, attn_smem);

    dim3 blk(256);
    proj_kernel<<<dim3(Ls/64, Bb, Hh), blk>>>(X, Wq, bq, gQ);
    proj_kernel<<<dim3(Ls/64, Bb, Hh), blk>>>(X, Wk, bk, gK);
    proj_kernel<<<dim3(Ls/64, Bb, Hh), blk>>>(X, Wv, bv, gV);
    attn_kernel<<<dim3(Ls/64, Bb*Hh), blk, attn_smem>>>();
    outproj_kernel<<<dim3((Bb*Ls)/64, Dm/64), blk>>>(Wo, bo, out);
}

// round 4
// speedup vs baseline: 2.6093x; 2.6093x over previous
#include <cuda_runtime.h>

#define Bb 2
#define Ls 2048
#define Dm 1024
#define Hh 16
#define Dk 64

// Scratch (allocation-free): Q,K,V,Z each B*H*L*Dk floats = 16 MB
__device__ float g_Q[Bb*Hh*Ls*Dk];
__device__ float g_K[Bb*Hh*Ls*Dk];
__device__ float g_V[Bb*Hh*Ls*Dk];
__device__ float g_Z[Bb*Hh*Ls*Dk];

// ---------------------------------------------------------------------------
// tf32 mma helpers
// ---------------------------------------------------------------------------
__device__ __forceinline__ float f2tf(float x) {
    unsigned r;
    asm("cvt.rna.tf32.f32 %0, %1;" : "=r"(r) : "f"(x));
    return __uint_as_float(r);
}

__device__ __forceinline__ void mma8(float* d, const unsigned* a, const unsigned* b) {
    asm volatile(
        "mma.sync.aligned.m16n8k8.row.col.f32.tf32.tf32.f32 "
        "{%0,%1,%2,%3}, {%4,%5,%6,%7}, {%8,%9}, {%0,%1,%2,%3};"
        : "+f"(d[0]), "+f"(d[1]), "+f"(d[2]), "+f"(d[3])
        : "r"(a[0]), "r"(a[1]), "r"(a[2]), "r"(a[3]),
          "r"(b[0]), "r"(b[1]));
}
#define BITS(p) __float_as_uint(p)

// ---------------------------------------------------------------------------
// Projection: out[b,h,l,k] = sum_d X[b,l,d] * W[h,d,k] + bias[h,k]
// Block: 128(l) x 64(k), BK=32. 8 warps, warp = 16 rows x 64 cols.
// Xs[128][36] (A, stride%32==4), Ws[32][72] (B, stride%32==8). Conflict-free.
// ---------------------------------------------------------------------------
__global__ void __launch_bounds__(256, 2)
proj_mma(const float* __restrict__ X, const float* __restrict__ W,
         const float* __restrict__ bias, float* __restrict__ out)
{
    __shared__ float Xs[128*36];
    __shared__ float Ws[32*72];
    const int ltile = blockIdx.x, b = blockIdx.y, h = blockIdx.z;
    const int t = threadIdx.x, wid = t >> 5, lane = t & 31;
    const int g = lane >> 2, c = lane & 3;
    const int m0 = wid * 16;
    const float* Xp = X + ((size_t)b*Ls + (size_t)ltile*128) * Dm;
    const float* Wp = W + (size_t)h*Dm*Dk;

    float acc[8][4] = {};
    for (int d0 = 0; d0 < Dm; d0 += 32) {
        __syncthreads();
#pragma unroll
        for (int i = 0; i < 4; i++) {           // X tile 128x32 -> 1024 f4
            int idx = t + i*256, r = idx >> 3, q = idx & 7;
            float4 v = *(const float4*)(Xp + (size_t)r*Dm + d0 + q*4);
            float* dst = Xs + r*36 + q*4;
            dst[0]=f2tf(v.x); dst[1]=f2tf(v.y); dst[2]=f2tf(v.z); dst[3]=f2tf(v.w);
        }
#pragma unroll
        for (int i = 0; i < 2; i++) {           // W tile 32x64 -> 512 f4
            int idx = t + i*256, r = idx >> 4, q = idx & 15;
            float4 v = *(const float4*)(Wp + (size_t)(d0+r)*Dk + q*4);
            float* dst = Ws + r*72 + q*4;
            dst[0]=f2tf(v.x); dst[1]=f2tf(v.y); dst[2]=f2tf(v.z); dst[3]=f2tf(v.w);
        }
        __syncthreads();
#pragma unroll
        for (int ks = 0; ks < 4; ks++) {
            const float* xb = Xs + (m0+g)*36 + ks*8 + c;
            unsigned a[4] = { BITS(xb[0]), BITS(xb[8*36]), BITS(xb[4]), BITS(xb[8*36+4]) };
#pragma unroll
            for (int ni = 0; ni < 8; ni++) {
                const float* wb = Ws + (ks*8+c)*72 + ni*8 + g;
                unsigned bb[2] = { BITS(wb[0]), BITS(wb[4*72]) };
                mma8(acc[ni], a, bb);
            }
        }
    }
    float* op = out + (((size_t)b*Hh + h)*Ls + (size_t)ltile*128)*Dk;
    const float* bp = bias + h*Dk;
#pragma unroll
    for (int ni = 0; ni < 8; ni++) {
        int k0 = ni*8 + 2*c;
        float b0 = bp[k0], b1 = bp[k0+1];
        float2 r0 = make_float2(acc[ni][0]+b0, acc[ni][1]+b1);
        float2 r1 = make_float2(acc[ni][2]+b0, acc[ni][3]+b1);
        *(float2*)(op + (size_t)(m0+g)*Dk + k0)   = r0;
        *(float2*)(op + (size_t)(m0+g+8)*Dk + k0) = r1;
    }
}

// ---------------------------------------------------------------------------
// Flash attention (tf32 mma): per (b*h, 128-row Q tile). Bc = 64.
// 8 warps, warp = 16 Q-rows x all 64 cols -> softmax fully warp-local.
// Qs[128][68], Ks[64][72], Vs[64][72], Ps[128][68] (Ps per-warp private rows).
// ---------------------------------------------------------------------------
__global__ void __launch_bounds__(256, 2) attn_mma()
{
    extern __shared__ float sm[];
    float* Qs = sm;                  // [128][68]
    float* Ks = Qs + 128*68;         // [64][72]
    float* Vs = Ks + 64*72;          // [64][72]
    float* Ps = Vs + 64*72;          // [128][68]
    const int bh = blockIdx.y, i0 = blockIdx.x * 128;
    const float* Qp = g_Q + ((size_t)bh*Ls + i0)*Dk;
    const float* Kp = g_K + (size_t)bh*Ls*Dk;
    const float* Vp = g_V + (size_t)bh*Ls*Dk;
    const int t = threadIdx.x, wid = t >> 5, lane = t & 31;
    const int g = lane >> 2, c = lane & 3;
    const int m0 = wid * 16;

    // Load Q (scale folded in): 128x64 = 2048 f4, 8/thread
#pragma unroll
    for (int i = 0; i < 8; i++) {
        int idx = t + i*256, r = idx >> 4, q = idx & 15;
        float4 v = *(const float4*)(Qp + (size_t)r*Dk + q*4);
        float* dst = Qs + r*68 + q*4;
        dst[0]=f2tf(v.x*0.125f); dst[1]=f2tf(v.y*0.125f);
        dst[2]=f2tf(v.z*0.125f); dst[3]=f2tf(v.w*0.125f);
    }

    float o[8][4] = {};
    float mrow[2] = {-1e30f, -1e30f}, lrow[2] = {0.f, 0.f};

    for (int j0 = 0; j0 < Ls; j0 += 64) {
        __syncthreads();
#pragma unroll
        for (int i = 0; i < 4; i++) {            // K,V tiles 64x64 each
            int idx = t + i*256, r = idx >> 4, q = idx & 15;
            float4 kv = *(const float4*)(Kp + (size_t)(j0+r)*Dk + q*4);
            float* kd = Ks + r*72 + q*4;
            kd[0]=f2tf(kv.x); kd[1]=f2tf(kv.y); kd[2]=f2tf(kv.z); kd[3]=f2tf(kv.w);
            float4 vv = *(const float4*)(Vp + (size_t)(j0+r)*Dk + q*4);
            float* vd = Vs + r*72 + q*4;
            vd[0]=f2tf(vv.x); vd[1]=f2tf(vv.y); vd[2]=f2tf(vv.z); vd[3]=f2tf(vv.w);
        }
        __syncthreads();

        // S = Q K^T : warp rows m0..m0+15, cols 0..63
        float s[8][4] = {};
#pragma unroll
        for (int ks = 0; ks < 8; ks++) {
            const float* qb = Qs + (m0+g)*68 + ks*8 + c;
            unsigned a[4] = { BITS(qb[0]), BITS(qb[8*68]), BITS(qb[4]), BITS(qb[8*68+4]) };
#pragma unroll
            for (int ni = 0; ni < 8; ni++) {
                const float* kb = Ks + (ni*8+g)*72 + ks*8 + c;
                unsigned bb[2] = { BITS(kb[0]), BITS(kb[4]) };
                mma8(s[ni], a, bb);
            }
        }
        // Online softmax: thread owns rows (m0+g) [elems 0,1] and (m0+g+8) [2,3]
#pragma unroll
        for (int rr = 0; rr < 2; rr++) {
            float mx = -1e30f;
#pragma unroll
            for (int ni = 0; ni < 8; ni++)
                mx = fmaxf(mx, fmaxf(s[ni][rr*2], s[ni][rr*2+1]));
            mx = fmaxf(mx, __shfl_xor_sync(0xffffffffu, mx, 1));
            mx = fmaxf(mx, __shfl_xor_sync(0xffffffffu, mx, 2));
            float mnew = fmaxf(mrow[rr], mx);
            float corr = __expf(mrow[rr] - mnew);
            float rs = 0.f;
#pragma unroll
            for (int ni = 0; ni < 8; ni++) {
                float p0 = __expf(s[ni][rr*2]   - mnew);
                float p1 = __expf(s[ni][rr*2+1] - mnew);
                s[ni][rr*2] = p0; s[ni][rr*2+1] = p1;
                rs += p0 + p1;
            }
            rs += __shfl_xor_sync(0xffffffffu, rs, 1);
            rs += __shfl_xor_sync(0xffffffffu, rs, 2);
            lrow[rr] = lrow[rr]*corr + rs;
            mrow[rr] = mnew;
#pragma unroll
            for (int ni = 0; ni < 8; ni++) {
                o[ni][rr*2]   *= corr;
                o[ni][rr*2+1] *= corr;
                float* pd = Ps + (m0+g+rr*8)*68 + ni*8 + 2*c;
                pd[0] = f2tf(s[ni][rr*2]);
                pd[1] = f2tf(s[ni][rr*2+1]);
            }
        }
        __syncwarp();   // Ps rows are warp-private; st->ld visibility only

        // O += P V
#pragma unroll
        for (int ks = 0; ks < 8; ks++) {
            const float* pb = Ps + (m0+g)*68 + ks*8 + c;
            unsigned a[4] = { BITS(pb[0]), BITS(pb[8*68]), BITS(pb[4]), BITS(pb[8*68+4]) };
#pragma unroll
            for (int ni = 0; ni < 8; ni++) {
                const float* vb = Vs + (ks*8+c)*72 + ni*8 + g;
                unsigned bb[2] = { BITS(vb[0]), BITS(vb[4*72]) };
                mma8(o[ni], a, bb);
            }
        }
    }
    float inv0 = 1.f / lrow[0], inv1 = 1.f / lrow[1];
    float* zp = g_Z + ((size_t)bh*Ls + i0)*Dk;
#pragma unroll
    for (int ni = 0; ni < 8; ni++) {
        int k0 = ni*8 + 2*c;
        *(float2*)(zp + (size_t)(m0+g)*Dk + k0)   = make_float2(o[ni][0]*inv0, o[ni][1]*inv0);
        *(float2*)(zp + (size_t)(m0+g+8)*Dk + k0) = make_float2(o[ni][2]*inv1, o[ni][3]*inv1);
    }
}

// ---------------------------------------------------------------------------
// Output projection, computed TRANSPOSED to avoid smem transposes:
// C'[d][l] = sum_e Wo[d][e] * Z[l][e];  out[l][d] = C'[d][l] + bo[d]
// Block: 128(d) x 128(l), BK=32. 8 warps as 4(d) x 2(l), warp 32x64.
// Wos[128][36] (A), Zs[128][40] (B, stride%32==8). Conflict-free, all f4 loads.
// ---------------------------------------------------------------------------
__global__ void __launch_bounds__(256, 2)
outproj_mma(const float* __restrict__ Wo, const float* __restrict__ bo,
            float* __restrict__ out)
{
    __shared__ float Wos[128*36];
    __shared__ float Zs[128*40];
    const int dt = blockIdx.y, rt = blockIdx.x;
    const int row0 = rt * 128;
    const int b = row0 >> 11, l0 = row0 & (Ls-1);
    const int t = threadIdx.x, wid = t >> 5, lane = t & 31;
    const int g = lane >> 2, c = lane & 3;
    const int m0 = (wid >> 1) * 32;      // d-offset of warp
    const int n0 = (wid & 1) * 64;       // l-offset of warp

    float acc[2][8][4] = {};
    for (int e0 = 0; e0 < Dm; e0 += 32) {
        __syncthreads();
        const int h = e0 >> 6, v0 = e0 & 63;
#pragma unroll
        for (int i = 0; i < 4; i++) {    // Z tile 128(l) x 32(e)
            int idx = t + i*256, r = idx >> 3, q = idx & 7;
            float4 v = *(const float4*)(g_Z + (((size_t)b*Hh + h)*Ls + l0 + r)*Dk + v0 + q*4);
            float* dst = Zs + r*40 + q*4;
            dst[0]=f2tf(v.x); dst[1]=f2tf(v.y); dst[2]=f2tf(v.z); dst[3]=f2tf(v.w);
        }
#pragma unroll
        for (int i = 0; i < 4; i++) {    // Wo tile 128(d) x 32(e)
            int idx = t + i*256, r = idx >> 3, q = idx & 7;
            float4 v = *(const float4*)(Wo + (size_t)(dt*128+r)*Dm + e0 + q*4);
            float* dst = Wos + r*36 + q*4;
            dst[0]=f2tf(v.x); dst[1]=f2tf(v.y); dst[2]=f2tf(v.z); dst[3]=f2tf(v.w);
        }
        __syncthreads();
#pragma unroll
        for (int ks = 0; ks < 4; ks++) {
            unsigned a[2][4];
#pragma unroll
            for (int mi = 0; mi < 2; mi++) {
                const float* wb = Wos + (m0+mi*16+g)*36 + ks*8 + c;
                a[mi][0]=BITS(wb[0]); a[mi][1]=BITS(wb[8*36]);
                a[mi][2]=BITS(wb[4]); a[mi][3]=BITS(wb[8*36+4]);
            }
#pragma unroll
            for (int ni = 0; ni < 8; ni++) {
                const float* zb = Zs + (n0+ni*8+g)*40 + ks*8 + c;
                unsigned bb[2] = { BITS(zb[0]), BITS(zb[4]) };
                mma8(acc[0][ni], a[0], bb);
                mma8(acc[1][ni], a[1], bb);
            }
        }
    }
#pragma unroll
    for (int mi = 0; mi < 2; mi++) {
        int d0 = dt*128 + m0 + mi*16 + g;
        float b0 = bo[d0], b1 = bo[d0+8];
#pragma unroll
        for (int ni = 0; ni < 8; ni++) {
            size_t l_base = (size_t)row0 + n0 + ni*8 + 2*c;
            out[l_base*Dm + d0]       = acc[mi][ni][0] + b0;
            out[(l_base+1)*Dm + d0]   = acc[mi][ni][1] + b0;
            out[l_base*Dm + d0+8]     = acc[mi][ni][2] + b1;
            out[(l_base+1)*Dm + d0+8] = acc[mi][ni][3] + b1;
        }
    }
}

// ---------------------------------------------------------------------------

extern "C" void kernel_launch(void* const* d_in, const int* in_sizes, int n_in,
                              void* d_out, int out_size)
{
    const float* X  = (const float*)d_in[0];
    const float* Wq = (const float*)d_in[1];
    const float* bq = (const float*)d_in[2];
    const float* Wk = (const float*)d_in[3];
    const float* bk = (const float*)d_in[4];
    const float* Wv = (const float*)d_in[5];
    const float* bv = (const float*)d_in[6];
    const float* Wo = (const float*)d_in[7];
    const float* bo = (const float*)d_in[8];
    float* out = (float*)d_out;

    float *gQ, *gK, *gV;
    cudaGetSymbolAddress((void**)&gQ, g_Q);
    cudaGetSymbolAddress((void**)&gK, g_K);
    cudaGetSymbolAddress((void**)&gV, g_V);

    const int attn_smem = (128*68 + 64*72 + 64*72 + 128*68) * 4;   // 106496 B
    cudaFuncSetAttribute(attn_mma, cudaFuncAttributeMaxDynamicSharedMemorySize, attn_smem);

    dim3 blk(256);
    proj_mma<<<dim3(Ls/128, Bb, Hh), blk>>>(X, Wq, bq, gQ);
    proj_mma<<<dim3(Ls/128, Bb, Hh), blk>>>(X, Wk, bk, gK);
    proj_mma<<<dim3(Ls/128, Bb, Hh), blk>>>(X, Wv, bv, gV);
    attn_mma<<<dim3(Ls/128, Bb*Hh), blk, attn_smem>>>();
    outproj_mma<<<dim3((Bb*Ls)/128, Dm/128), blk>>>(Wo, bo, out);
}